// round 11
// baseline (speedup 1.0000x reference)
#include <cuda_runtime.h>
#include <cuda_fp16.h>

// samples: (16,3,480,864) f32 ; encoded: (1,16,480,864) i32 ; n_pixels=2e6
// Both resizes are identity. Task: fp16-round -> segment mean -> gather.
// Output: float32 (values are fp16-rounded means).

#define N_PIX  2000000
#define T_DIM  16
#define H_DIM  480
#define W_DIM  864
#define HW     (H_DIM * W_DIM)        // 414720  (divisible by 8)
#define NPOS   (T_DIM * HW)           // 6635520
#define N_SAMP (T_DIM * 3 * HW)       // 19906560

__device__ float4  g_acc[N_PIX];      // (s0, s1, s2, count)  32 MB
__device__ ushort4 g_res[N_PIX];      // packed half3 mean     16 MB (L2-resident)

// ---------------------------------------------------------------------------
// 4 consecutive positions per thread; one v4.f32 RED per position.
__global__ void scatter_kernel(const float* __restrict__ samples,
                               const int*   __restrict__ enc) {
    int j = blockIdx.x * blockDim.x + threadIdx.x;
    if (j >= NPOS / 4) return;
    int i = 4 * j;
    int t = i / HW;
    int p = i - t * HW;

    const float* s = samples + (size_t)t * 3 * HW + p;
    float4 c0 = __ldcs(reinterpret_cast<const float4*>(s));
    float4 c1 = __ldcs(reinterpret_cast<const float4*>(s + HW));
    float4 c2 = __ldcs(reinterpret_cast<const float4*>(s + 2 * HW));
    int4 idx4 = __ldcs(reinterpret_cast<const int4*>(enc + i));

    // fp16-round before accumulation (matches reference precision chain)
    #define R16(x) __half2float(__float2half_rn(x))
    float a0x = R16(c0.x), a0y = R16(c0.y), a0z = R16(c0.z), a0w = R16(c0.w);
    float a1x = R16(c1.x), a1y = R16(c1.y), a1z = R16(c1.z), a1w = R16(c1.w);
    float a2x = R16(c2.x), a2y = R16(c2.y), a2z = R16(c2.z), a2w = R16(c2.w);
    #undef R16

    #define RED4(ix, v0, v1, v2)                                              \
        asm volatile("red.global.add.v4.f32 [%0], {%1, %2, %3, %4};"          \
                     :: "l"(&g_acc[ix]), "f"(v0), "f"(v1), "f"(v2), "f"(1.0f) \
                     : "memory")
    RED4(idx4.x, a0x, a1x, a2x);
    RED4(idx4.y, a0y, a1y, a2y);
    RED4(idx4.z, a0z, a1z, a2z);
    RED4(idx4.w, a0w, a1w, a2w);
    #undef RED4
}

// ---------------------------------------------------------------------------
// One thread per bucket: divide once, pack mean to half3 (8B compact table).
__global__ void finalize_kernel() {
    int i = blockIdx.x * blockDim.x + threadIdx.x;
    if (i >= N_PIX) return;

    float4 a = __ldcs(&g_acc[i]);
    float c = (a.w > 0.f) ? a.w : 1.0f;
    float inv = 1.0f / c;

    ushort4 r;
    r.x = __half_as_ushort(__float2half_rn(a.x * inv));
    r.y = __half_as_ushort(__float2half_rn(a.y * inv));
    r.z = __half_as_ushort(__float2half_rn(a.z * inv));
    r.w = 0;
    g_res[i] = r;
}

// ---------------------------------------------------------------------------
// R4 shape: 4 positions/thread, low regs, high occupancy. Streaming hints on
// enc (__ldcs) and output (__stcs) keep the 16 MB table resident in L2.
__global__ void gather_kernel(const int* __restrict__ enc,
                              float*     __restrict__ out) {
    int j = blockIdx.x * blockDim.x + threadIdx.x;
    if (j >= NPOS / 4) return;
    int i = 4 * j;
    int t = i / HW;
    int p = i - t * HW;

    int4 idx4 = __ldcs(reinterpret_cast<const int4*>(enc + i));
    ushort4 ra = __ldg(&g_res[idx4.x]);
    ushort4 rb = __ldg(&g_res[idx4.y]);
    ushort4 rc = __ldg(&g_res[idx4.z]);
    ushort4 rd = __ldg(&g_res[idx4.w]);

    float* o = out + (size_t)t * 3 * HW + p;
    #define H2F(u) __half2float(__ushort_as_half(u))
    __stcs(reinterpret_cast<float4*>(o),
           make_float4(H2F(ra.x), H2F(rb.x), H2F(rc.x), H2F(rd.x)));
    __stcs(reinterpret_cast<float4*>(o + HW),
           make_float4(H2F(ra.y), H2F(rb.y), H2F(rc.y), H2F(rd.y)));
    __stcs(reinterpret_cast<float4*>(o + 2 * HW),
           make_float4(H2F(ra.z), H2F(rb.z), H2F(rc.z), H2F(rd.z)));
    #undef H2F
}

// ---------------------------------------------------------------------------
extern "C" void kernel_launch(void* const* d_in, const int* in_sizes, int n_in,
                              void* d_out, int out_size) {
    const float* samples = nullptr;
    const int*   enc     = nullptr;
    for (int k = 0; k < n_in; k++) {
        if (in_sizes[k] == N_SAMP)    samples = (const float*)d_in[k];
        else if (in_sizes[k] == NPOS) enc     = (const int*)d_in[k];
    }
    float* out = (float*)d_out;

    // Zero the accumulator with a memset node (driver-optimal).
    void* acc_ptr = nullptr;
    cudaGetSymbolAddress(&acc_ptr, g_acc);
    cudaMemsetAsync(acc_ptr, 0, (size_t)N_PIX * sizeof(float4));

    const int TPB = 256;
    scatter_kernel<<<(NPOS / 4 + TPB - 1) / TPB, TPB>>>(samples, enc);
    finalize_kernel<<<(N_PIX + TPB - 1) / TPB, TPB>>>();
    gather_kernel<<<(NPOS / 4 + TPB - 1) / TPB, TPB>>>(enc, out);
}

// round 12
// speedup vs baseline: 1.0224x; 1.0224x over previous
#include <cuda_runtime.h>
#include <cuda_fp16.h>

// samples: (16,3,480,864) f32 ; encoded: (1,16,480,864) i32 ; n_pixels=2e6
// Both resizes are identity. Task: fp16-round -> segment mean -> gather.
// Output: float32 (values are fp16-rounded means).

#define N_PIX  2000000
#define T_DIM  16
#define H_DIM  480
#define W_DIM  864
#define HW     (H_DIM * W_DIM)        // 414720  (divisible by 8)
#define NPOS   (T_DIM * HW)           // 6635520
#define N_SAMP (T_DIM * 3 * HW)       // 19906560

__device__ float4  g_acc[N_PIX];      // (s0, s1, s2, count)  32 MB
__device__ ushort4 g_res[N_PIX];      // packed half3 mean     16 MB (L2-resident)

// ---------------------------------------------------------------------------
// R4-proven scatter: 4 consecutive positions per thread, plain LDG.128 loads,
// one red.global.add.v4.f32 per position (sum3 + count fused).
__global__ void scatter_kernel(const float* __restrict__ samples,
                               const int*   __restrict__ enc) {
    int j = blockIdx.x * blockDim.x + threadIdx.x;
    if (j >= NPOS / 4) return;
    int i = 4 * j;
    int t = i / HW;
    int p = i - t * HW;

    const float* s = samples + (size_t)t * 3 * HW + p;
    float4 c0 = *reinterpret_cast<const float4*>(s);
    float4 c1 = *reinterpret_cast<const float4*>(s + HW);
    float4 c2 = *reinterpret_cast<const float4*>(s + 2 * HW);
    int4 idx4 = *reinterpret_cast<const int4*>(enc + i);

    // fp16-round before accumulation (matches reference precision chain)
    #define R16(x) __half2float(__float2half_rn(x))
    float a0x = R16(c0.x), a0y = R16(c0.y), a0z = R16(c0.z), a0w = R16(c0.w);
    float a1x = R16(c1.x), a1y = R16(c1.y), a1z = R16(c1.z), a1w = R16(c1.w);
    float a2x = R16(c2.x), a2y = R16(c2.y), a2z = R16(c2.z), a2w = R16(c2.w);
    #undef R16

    #define RED4(ix, v0, v1, v2)                                              \
        asm volatile("red.global.add.v4.f32 [%0], {%1, %2, %3, %4};"          \
                     :: "l"(&g_acc[ix]), "f"(v0), "f"(v1), "f"(v2), "f"(1.0f) \
                     : "memory")
    RED4(idx4.x, a0x, a1x, a2x);
    RED4(idx4.y, a0y, a1y, a2y);
    RED4(idx4.z, a0z, a1z, a2z);
    RED4(idx4.w, a0w, a1w, a2w);
    #undef RED4
}

// ---------------------------------------------------------------------------
// 2 buckets per thread: 2x float4 reads, one 16B packed write.
__global__ void finalize_kernel() {
    int j = blockIdx.x * blockDim.x + threadIdx.x;
    if (j >= N_PIX / 2) return;
    int i = 2 * j;

    float4 a = g_acc[i];
    float4 b = g_acc[i + 1];
    float ia = 1.0f / ((a.w > 0.f) ? a.w : 1.0f);
    float ib = 1.0f / ((b.w > 0.f) ? b.w : 1.0f);

    ushort4 ra, rb;
    ra.x = __half_as_ushort(__float2half_rn(a.x * ia));
    ra.y = __half_as_ushort(__float2half_rn(a.y * ia));
    ra.z = __half_as_ushort(__float2half_rn(a.z * ia));
    ra.w = 0;
    rb.x = __half_as_ushort(__float2half_rn(b.x * ib));
    rb.y = __half_as_ushort(__float2half_rn(b.y * ib));
    rb.z = __half_as_ushort(__float2half_rn(b.z * ib));
    rb.w = 0;

    // one 16B store covering both buckets
    uint4 pk;
    pk.x = (unsigned)ra.x | ((unsigned)ra.y << 16);
    pk.y = (unsigned)ra.z;                         // ra.w == 0
    pk.z = (unsigned)rb.x | ((unsigned)rb.y << 16);
    pk.w = (unsigned)rb.z;                         // rb.w == 0
    *reinterpret_cast<uint4*>(&g_res[i]) = pk;
}

// ---------------------------------------------------------------------------
// R4-proven gather: 4 positions/thread, plain loads/stores, low regs.
__global__ void gather_kernel(const int* __restrict__ enc,
                              float*     __restrict__ out) {
    int j = blockIdx.x * blockDim.x + threadIdx.x;
    if (j >= NPOS / 4) return;
    int i = 4 * j;
    int t = i / HW;
    int p = i - t * HW;

    int4 idx4 = *reinterpret_cast<const int4*>(enc + i);
    ushort4 ra = __ldg(&g_res[idx4.x]);
    ushort4 rb = __ldg(&g_res[idx4.y]);
    ushort4 rc = __ldg(&g_res[idx4.z]);
    ushort4 rd = __ldg(&g_res[idx4.w]);

    float* o = out + (size_t)t * 3 * HW + p;
    #define H2F(u) __half2float(__ushort_as_half(u))
    *reinterpret_cast<float4*>(o) =
        make_float4(H2F(ra.x), H2F(rb.x), H2F(rc.x), H2F(rd.x));
    *reinterpret_cast<float4*>(o + HW) =
        make_float4(H2F(ra.y), H2F(rb.y), H2F(rc.y), H2F(rd.y));
    *reinterpret_cast<float4*>(o + 2 * HW) =
        make_float4(H2F(ra.z), H2F(rb.z), H2F(rc.z), H2F(rd.z));
    #undef H2F
}

// ---------------------------------------------------------------------------
extern "C" void kernel_launch(void* const* d_in, const int* in_sizes, int n_in,
                              void* d_out, int out_size) {
    const float* samples = nullptr;
    const int*   enc     = nullptr;
    for (int k = 0; k < n_in; k++) {
        if (in_sizes[k] == N_SAMP)    samples = (const float*)d_in[k];
        else if (in_sizes[k] == NPOS) enc     = (const int*)d_in[k];
    }
    float* out = (float*)d_out;

    // Zero the accumulator with a memset node (driver-optimal).
    void* acc_ptr = nullptr;
    cudaGetSymbolAddress(&acc_ptr, g_acc);
    cudaMemsetAsync(acc_ptr, 0, (size_t)N_PIX * sizeof(float4));

    const int TPB = 256;
    scatter_kernel<<<(NPOS / 4 + TPB - 1) / TPB, TPB>>>(samples, enc);
    finalize_kernel<<<(N_PIX / 2 + TPB - 1) / TPB, TPB>>>();
    gather_kernel<<<(NPOS / 4 + TPB - 1) / TPB, TPB>>>(enc, out);
}

// round 13
// speedup vs baseline: 1.1280x; 1.1032x over previous
#include <cuda_runtime.h>
#include <cuda_fp16.h>

// samples: (16,3,480,864) f32 ; encoded: (1,16,480,864) i32 ; n_pixels=2e6
// Both resizes are identity. Task: fp16-round -> fp16 segment mean -> gather.
// Output: float32 (values are fp16 means, promoted).
// Accumulator is fp16 (matches reference's fp16 segment_sum) via f16x2 REDs.

#define N_PIX  2000000
#define T_DIM  16
#define H_DIM  480
#define W_DIM  864
#define HW     (H_DIM * W_DIM)        // 414720  (divisible by 8)
#define NPOS   (T_DIM * HW)           // 6635520
#define N_SAMP (T_DIM * 3 * HW)       // 19906560

// Per bucket 8 bytes: {h0,h1} f16x2 | {h2,count} f16x2.  16 MB — L2-hot.
__device__ uint2 g_acc[N_PIX];

static __device__ __forceinline__ unsigned h2_to_u32(__half2 h) {
    unsigned u; memcpy(&u, &h, 4); return u;
}
static __device__ __forceinline__ __half2 u32_to_h2(unsigned u) {
    __half2 h; memcpy(&h, &u, 4); return h;
}

// ---------------------------------------------------------------------------
// 4 consecutive positions per thread; one 8-byte v2.f16x2 RED per position
// (3 channel sums + count in a single L2 RMW).
__global__ void scatter_kernel(const float* __restrict__ samples,
                               const int*   __restrict__ enc) {
    int j = blockIdx.x * blockDim.x + threadIdx.x;
    if (j >= NPOS / 4) return;
    int i = 4 * j;
    int t = i / HW;
    int p = i - t * HW;

    const float* s = samples + (size_t)t * 3 * HW + p;
    float4 c0 = *reinterpret_cast<const float4*>(s);
    float4 c1 = *reinterpret_cast<const float4*>(s + HW);
    float4 c2 = *reinterpret_cast<const float4*>(s + 2 * HW);
    int4 idx4 = *reinterpret_cast<const int4*>(enc + i);

    // fp16 rounding matches the reference's .astype(float16) before segment_sum
    #define PK(a, b) h2_to_u32(__floats2half2_rn((a), (b)))
    unsigned p01_x = PK(c0.x, c1.x), p2c_x = PK(c2.x, 1.0f);
    unsigned p01_y = PK(c0.y, c1.y), p2c_y = PK(c2.y, 1.0f);
    unsigned p01_z = PK(c0.z, c1.z), p2c_z = PK(c2.z, 1.0f);
    unsigned p01_w = PK(c0.w, c1.w), p2c_w = PK(c2.w, 1.0f);
    #undef PK

    #define RED2(ix, r0, r1)                                                  \
        asm volatile("red.global.add.noftz.v2.f16x2 [%0], {%1, %2};"          \
                     :: "l"(&g_acc[ix]), "r"(r0), "r"(r1) : "memory")
    RED2(idx4.x, p01_x, p2c_x);
    RED2(idx4.y, p01_y, p2c_y);
    RED2(idx4.z, p01_z, p2c_z);
    RED2(idx4.w, p01_w, p2c_w);
    #undef RED2
}

// ---------------------------------------------------------------------------
// Fused divide + gather, occupancy-safe: 4 positions/thread (R4 shape),
// 8B random read per position (one 32B sector/lane — same as a result table),
// inline mean computation, 3x float4 coalesced stores.
__global__ void gather_kernel(const int* __restrict__ enc,
                              float*     __restrict__ out) {
    int j = blockIdx.x * blockDim.x + threadIdx.x;
    if (j >= NPOS / 4) return;
    int i = 4 * j;
    int t = i / HW;
    int p = i - t * HW;

    int4 idx4 = *reinterpret_cast<const int4*>(enc + i);
    uint2 a = __ldg(&g_acc[idx4.x]);
    uint2 b = __ldg(&g_acc[idx4.y]);
    uint2 c = __ldg(&g_acc[idx4.z]);
    uint2 d = __ldg(&g_acc[idx4.w]);

    float r0[4], r1[4], r2[4];
    #define FIN(k, A) {                                                       \
        __half2 s01 = u32_to_h2((A).x);                                       \
        __half2 s2c = u32_to_h2((A).y);                                       \
        float inv = 1.0f / __half2float(__high2half(s2c)); /* count >= 1 */   \
        r0[k] = __half2float(__float2half_rn(__half2float(__low2half(s01))  * inv)); \
        r1[k] = __half2float(__float2half_rn(__half2float(__high2half(s01)) * inv)); \
        r2[k] = __half2float(__float2half_rn(__half2float(__low2half(s2c))  * inv)); \
    }
    FIN(0, a) FIN(1, b) FIN(2, c) FIN(3, d)
    #undef FIN

    float* o = out + (size_t)t * 3 * HW + p;
    *reinterpret_cast<float4*>(o)          = make_float4(r0[0], r0[1], r0[2], r0[3]);
    *reinterpret_cast<float4*>(o + HW)     = make_float4(r1[0], r1[1], r1[2], r1[3]);
    *reinterpret_cast<float4*>(o + 2 * HW) = make_float4(r2[0], r2[1], r2[2], r2[3]);
}

// ---------------------------------------------------------------------------
extern "C" void kernel_launch(void* const* d_in, const int* in_sizes, int n_in,
                              void* d_out, int out_size) {
    const float* samples = nullptr;
    const int*   enc     = nullptr;
    for (int k = 0; k < n_in; k++) {
        if (in_sizes[k] == N_SAMP)    samples = (const float*)d_in[k];
        else if (in_sizes[k] == NPOS) enc     = (const int*)d_in[k];
    }
    float* out = (float*)d_out;

    // Zero the 16 MB accumulator with a memset node.
    void* acc_ptr = nullptr;
    cudaGetSymbolAddress(&acc_ptr, g_acc);
    cudaMemsetAsync(acc_ptr, 0, (size_t)N_PIX * sizeof(uint2));

    const int TPB = 256;
    scatter_kernel<<<(NPOS / 4 + TPB - 1) / TPB, TPB>>>(samples, enc);
    gather_kernel<<<(NPOS / 4 + TPB - 1) / TPB, TPB>>>(enc, out);
}